// round 16
// baseline (speedup 1.0000x reference)
#include <cuda_runtime.h>
#include <cuda_bf16.h>
#include <math.h>
#include <stdint.h>

#define SQ 68            // padded smem stride for Q[i][c], c=0..63
#define HH 0.025f        // 0.5*STEP
#define HS 0.05f         // STEP

__device__ float g_M [4096];
__device__ float g_MU[8192];
__device__ float g_Y [8192];
__device__ float g_BETA[18];
__device__ float g_DBETA[17];
__device__ unsigned g_KEYS[34];
__device__ float g_SLW[131072];   // [b][n]

__device__ __forceinline__ uint2 tf2x32(unsigned k0, unsigned k1,
                                        unsigned c0, unsigned c1) {
    unsigned ks2 = k0 ^ k1 ^ 0x1BD11BDAu;
    unsigned x0 = c0 + k0, x1 = c1 + k1;
#define TFR(r) { x0 += x1; x1 = (x1<<(r))|(x1>>(32-(r))); x1 ^= x0; }
    TFR(13) TFR(15) TFR(26) TFR(6)  x0 += k1;  x1 += ks2 + 1u;
    TFR(17) TFR(29) TFR(16) TFR(24) x0 += ks2; x1 += k0 + 2u;
    TFR(13) TFR(15) TFR(26) TFR(6)  x0 += k0;  x1 += k1 + 3u;
    TFR(17) TFR(29) TFR(16) TFR(24) x0 += k1;  x1 += ks2 + 4u;
    TFR(13) TFR(15) TFR(26) TFR(6)  x0 += ks2; x1 += k0 + 5u;
#undef TFR
    return make_uint2(x0, x1);
}

// partitionable-mode 32-bit random bits for flat index i (hi word = 0 here)
__device__ __forceinline__ unsigned tf_bits(unsigned k0, unsigned k1, unsigned i) {
    uint2 h = tf2x32(k0, k1, 0u, i);
    return h.x ^ h.y;
}

__device__ __forceinline__ float bits2normal(unsigned bits) {
    const float LO = -0x1.fffffep-1f;
    float f = __uint_as_float((bits >> 9) | 0x3F800000u) - 1.0f;
    float u = fmaxf(LO, f * 2.0f + LO);
    float w = -log1pf(-u * u), p;
    if (w < 5.0f) {
        w -= 2.5f;
        p = 2.81022636e-08f;
        p = fmaf(p, w, 3.43273939e-07f);  p = fmaf(p, w, -3.5233877e-06f);
        p = fmaf(p, w, -4.39150654e-06f); p = fmaf(p, w, 0.00021858087f);
        p = fmaf(p, w, -0.00125372503f);  p = fmaf(p, w, -0.00417768164f);
        p = fmaf(p, w, 0.246640727f);     p = fmaf(p, w, 1.50140941f);
    } else {
        w = sqrtf(w) - 3.0f;
        p = -0.000200214257f;
        p = fmaf(p, w, 0.000100950558f);  p = fmaf(p, w, 0.00134934322f);
        p = fmaf(p, w, -0.00367342844f);  p = fmaf(p, w, 0.00573950773f);
        p = fmaf(p, w, -0.0076224613f);   p = fmaf(p, w, 0.00943887047f);
        p = fmaf(p, w, 1.00167406f);      p = fmaf(p, w, 2.83297682f);
    }
    return 1.41421356237f * (p * u);
}

// ---------------- prep: M, mu, y, betas, keys -------------------------------
__global__ void prep_k(const float* __restrict__ x,
                       const float* __restrict__ Wenc,
                       const float* __restrict__ Wdec) {
    int idx = blockIdx.x * 256 + threadIdx.x;
    if (idx < 4096) {
        int i = idx >> 6, j = idx & 63;
        float s = 0.f;
        #pragma unroll 8
        for (int c = 0; c < 64; ++c) s = fmaf(Wdec[i*64+c], Wdec[j*64+c], s);
        g_M[idx] = s;
    } else if (idx < 12288) {
        int e = idx - 4096, b = e >> 6, d = e & 63;
        float smu = 0.f, sy = 0.f;
        #pragma unroll 8
        for (int c = 0; c < 64; ++c) {
            float xv = x[b*64+c];
            smu = fmaf(xv, Wenc[c*64+d], smu);
            sy  = fmaf(xv, Wdec[d*64+c], sy);
        }
        g_MU[e] = smu; g_Y[e] = sy;
    } else if (idx == 12288) {
        double bb[18];
        for (int i = 0; i < 18; ++i) {
            double z = 4.0 * (2.0 * ((double)i / 17.0) - 1.0);
            bb[i] = 1.0 / (1.0 + exp(-z));
        }
        double b0 = bb[0], sc = bb[17] - bb[0];
        for (int i = 0; i < 18; ++i) g_BETA[i] = (float)((bb[i]-b0)/sc);
        for (int i = 0; i < 17; ++i)
            g_DBETA[i] = (float)(((bb[i+1]-b0)/sc) - ((bb[i]-b0)/sc));
        for (int k = 1; k <= 16; ++k) {
            uint2 r = tf2x32(0u, 42u, 0u, (unsigned)k);  // fold_in(key(42), k)
            g_KEYS[2*k] = r.x; g_KEYS[2*k+1] = r.y;
        }
    }
}

// ---------------- main: 64 chains/block, fixed b ----------------------------
__global__ void __launch_bounds__(128)
ais_main(const float* __restrict__ qn) {
    __shared__ float sQ[64 * SQ];
    __shared__ float sM[4096];
    const int tid = threadIdx.x;
    const int jg = tid & 7, cq = tid >> 3;        // cq 0..15
    const int b = blockIdx.x, n0 = blockIdx.y * 32;
    const int j0 = jg * 8;

    for (int i = tid; i < 4096; i += 128) sM[i] = g_M[i];

    float mu8[8], y8[8];
    {
        float4 a = *(const float4*)&g_MU[b*64 + j0];
        float4 c = *(const float4*)&g_MU[b*64 + j0 + 4];
        mu8[0]=a.x; mu8[1]=a.y; mu8[2]=a.z; mu8[3]=a.w;
        mu8[4]=c.x; mu8[5]=c.y; mu8[6]=c.z; mu8[7]=c.w;
        float4 d = *(const float4*)&g_Y[b*64 + j0];
        float4 e = *(const float4*)&g_Y[b*64 + j0 + 4];
        y8[0]=d.x; y8[1]=d.y; y8[2]=d.z; y8[3]=d.w;
        y8[4]=e.x; y8[5]=e.y; y8[6]=e.z; y8[7]=e.w;
    }

    int nn[4];
    #pragma unroll
    for (int m = 0; m < 4; ++m) nn[m] = n0 + 2*cq + (m >> 1) + (m & 1)*512;

    float q[4][8], p[4][8], t[4][8], slw[4];
    #pragma unroll
    for (int m = 0; m < 4; ++m) {
        const float* src = qn + (size_t)nn[m]*8192 + b*64 + j0;
        float4 a = *(const float4*)src, c = *(const float4*)(src + 4);
        q[m][0]=mu8[0]+a.x; q[m][1]=mu8[1]+a.y; q[m][2]=mu8[2]+a.z; q[m][3]=mu8[3]+a.w;
        q[m][4]=mu8[4]+c.x; q[m][5]=mu8[5]+c.y; q[m][6]=mu8[6]+c.z; q[m][7]=mu8[7]+c.w;
        slw[m] = 0.f;
    }

#define PUSHQ() do { __syncthreads();                                        \
    _Pragma("unroll") for (int e = 0; e < 8; ++e) {                          \
        float4 v4 = make_float4(q[0][e], q[1][e], q[2][e], q[3][e]);         \
        *(float4*)&sQ[(j0 + e)*SQ + cq*4] = v4; }                            \
    __syncthreads(); } while (0)

#define MATVEC() do {                                                        \
    _Pragma("unroll") for (int m = 0; m < 4; ++m)                            \
    _Pragma("unroll") for (int e = 0; e < 8; ++e) t[m][e] = 0.f;             \
    _Pragma("unroll 4") for (int i = 0; i < 64; ++i) {                       \
        float4 qv = *(const float4*)&sQ[i*SQ + cq*4];                        \
        float4 m0 = *(const float4*)&sM[i*64 + j0];                          \
        float4 m1 = *(const float4*)&sM[i*64 + j0 + 4];                      \
        float qa[4] = {qv.x, qv.y, qv.z, qv.w};                              \
        float mm[8] = {m0.x,m0.y,m0.z,m0.w,m1.x,m1.y,m1.z,m1.w};             \
        _Pragma("unroll") for (int m = 0; m < 4; ++m)                        \
        _Pragma("unroll") for (int e = 0; e < 8; ++e)                        \
            t[m][e] = fmaf(qa[m], mm[e], t[m][e]);                           \
    } } while (0)

#define ADDW(DB) do {                                                        \
    float wc[4];                                                             \
    _Pragma("unroll") for (int m = 0; m < 4; ++m) { wc[m] = 0.f;             \
        _Pragma("unroll") for (int e = 0; e < 8; ++e)                        \
            wc[m] = fmaf(q[m][e], (y8[e]-mu8[e]) - 0.5f*t[m][e], wc[m]); }   \
    _Pragma("unroll") for (int off = 1; off < 8; off <<= 1)                  \
        _Pragma("unroll") for (int m = 0; m < 4; ++m)                        \
            wc[m] += __shfl_xor_sync(0xffffffffu, wc[m], off);               \
    _Pragma("unroll") for (int m = 0; m < 4; ++m)                            \
        slw[m] = fmaf((DB), wc[m], slw[m]); } while (0)

    PUSHQ();
    MATVEC();
    ADDW(g_DBETA[0]);

    for (int k = 1; k <= 16; ++k) {
        const float bk = g_BETA[k], db = g_DBETA[k];
        const unsigned K0 = g_KEYS[2*k], K1 = g_KEYS[2*k+1];
        // momentum resample: JAX partitionable threefry, counter (0, flat_idx),
        // bits = x0 ^ x1, one hash per element
        #pragma unroll
        for (int m = 0; m < 4; ++m) {
            unsigned base = (unsigned)nn[m]*8192u + (unsigned)b*64u + (unsigned)j0;
            #pragma unroll
            for (int e = 0; e < 8; ++e)
                p[m][e] = bits2normal(tf_bits(K0, K1, base + e));
        }
        float a8[8];
        #pragma unroll
        for (int e = 0; e < 8; ++e) a8[e] = fmaf(bk, y8[e]-mu8[e], mu8[e]);
        #pragma unroll 1
        for (int leap = 0; leap < 3; ++leap) {
            #pragma unroll
            for (int m = 0; m < 4; ++m)
            #pragma unroll
            for (int e = 0; e < 8; ++e) {
                float g = a8[e] - fmaf(bk, t[m][e], q[m][e]);
                p[m][e] = fmaf(HH, g, p[m][e]);
                q[m][e] = fmaf(HS, p[m][e], q[m][e]);
            }
            PUSHQ();
            MATVEC();
            #pragma unroll
            for (int m = 0; m < 4; ++m)
            #pragma unroll
            for (int e = 0; e < 8; ++e) {
                float g = a8[e] - fmaf(bk, t[m][e], q[m][e]);
                p[m][e] = fmaf(HH, g, p[m][e]);
            }
        }
        ADDW(db);
    }

    if (jg == 0) {
        #pragma unroll
        for (int m = 0; m < 4; ++m) g_SLW[b*1024 + nn[m]] = slw[m];
    }
}

// ---------------- logsumexp over n, + c_b -----------------------------------
__global__ void lse_k(const float* __restrict__ x, float* __restrict__ out) {
    __shared__ float red[256];
    const int b = blockIdx.x, tid = threadIdx.x;
    float part = 0.f;
    for (int d = tid; d < 64; d += 256) {
        float xv = x[b*64+d], mv = g_MU[b*64+d];
        part += 0.5f * (mv*mv - xv*xv);
    }
    red[tid] = part; __syncthreads();
    for (int s = 128; s > 0; s >>= 1) { if (tid < s) red[tid] += red[tid+s]; __syncthreads(); }
    float cb = red[0] - 32.0f * 1.8378770664093453f;
    __syncthreads();
    float mx = -1e30f;
    for (int i = tid; i < 1024; i += 256) mx = fmaxf(mx, g_SLW[b*1024+i]);
    red[tid] = mx; __syncthreads();
    for (int s = 128; s > 0; s >>= 1) { if (tid < s) red[tid] = fmaxf(red[tid], red[tid+s]); __syncthreads(); }
    mx = red[0]; __syncthreads();
    float sum = 0.f;
    for (int i = tid; i < 1024; i += 256) sum += expf(g_SLW[b*1024+i] - mx);
    red[tid] = sum; __syncthreads();
    for (int s = 128; s > 0; s >>= 1) { if (tid < s) red[tid] += red[tid+s]; __syncthreads(); }
    if (tid == 0) out[b] = cb + mx + logf(red[0]) - 6.931471805599453f; // log 1024
}

extern "C" void kernel_launch(void* const* d_in, const int* in_sizes, int n_in,
                              void* d_out, int out_size) {
    const float* x    = (const float*)d_in[0];
    const float* Wenc = (const float*)d_in[1];
    const float* Wdec = (const float*)d_in[2];
    const float* qn   = (const float*)d_in[3];
    float* out = (float*)d_out;
    (void)in_sizes; (void)n_in; (void)out_size;

    prep_k<<<49, 256>>>(x, Wenc, Wdec);
    ais_main<<<dim3(128, 16), 128>>>(qn);
    lse_k<<<128, 256>>>(x, out);
}